// round 1
// baseline (speedup 1.0000x reference)
#include <cuda_runtime.h>
#include <math.h>

// ---------------- problem constants ----------------
#define B_    32
#define HH    56
#define WW_   56
#define C_    384
#define D_    1536
#define H3_   1152
#define NTOK  100352          // B*H*W = 32*56*56
#define NWIN  2048            // B * 64
#define WS_   7
#define N_    49
#define NH_   4
#define HD_   96

// ---------------- scratch (device globals; no allocs allowed) ----------------
__device__ float g_hwin[(size_t)NTOK * C_];   // LN1 + rolled + window-partitioned
__device__ float g_qkv [(size_t)NTOK * H3_];  // qkv projection
__device__ float g_attn[(size_t)NTOK * C_];   // attention output (window layout)
__device__ float g_owin[(size_t)NTOK * C_];   // proj output (window layout)
__device__ float g_x1  [(size_t)NTOK * C_];   // x + attn branch (b,h,w,c layout)
__device__ float g_h2  [(size_t)NTOK * C_];   // LN2 output
__device__ float g_m1  [(size_t)NTOK * D_];   // fc1+gelu output, then LN3 in-place

// ---------------- block reduce (sum, sumsq) ----------------
__device__ __forceinline__ void blockReduce2(float &a, float &b) {
    #pragma unroll
    for (int o = 16; o > 0; o >>= 1) {
        a += __shfl_down_sync(0xffffffffu, a, o);
        b += __shfl_down_sync(0xffffffffu, b, o);
    }
    __shared__ float sa[32], sb[32];
    int lane = threadIdx.x & 31, wid = threadIdx.x >> 5;
    if (lane == 0) { sa[wid] = a; sb[wid] = b; }
    __syncthreads();
    int nw = blockDim.x >> 5;
    if (wid == 0) {
        a = (lane < nw) ? sa[lane] : 0.f;
        b = (lane < nw) ? sb[lane] : 0.f;
        #pragma unroll
        for (int o = 16; o > 0; o >>= 1) {
            a += __shfl_down_sync(0xffffffffu, a, o);
            b += __shfl_down_sync(0xffffffffu, b, o);
        }
        if (lane == 0) { sa[0] = a; sb[0] = b; }
    }
    __syncthreads();
    a = sa[0]; b = sb[0];
}

// ---------------- K1: LN1 + roll(-3,-3) + window partition ----------------
__global__ void ln1_part(const float* __restrict__ x,
                         const float* __restrict__ g, const float* __restrict__ bt) {
    int t = blockIdx.x;                    // token (b,h,w) flat
    int bb = t / 3136, rem = t % 3136, h = rem / 56, w = rem % 56;
    const float* xi = x + (size_t)t * C_;
    float s = 0.f, s2 = 0.f;
    for (int c = threadIdx.x; c < C_; c += blockDim.x) { float v = xi[c]; s += v; s2 += v * v; }
    blockReduce2(s, s2);
    float mean = s * (1.f / C_);
    float inv  = rsqrtf(s2 * (1.f / C_) - mean * mean + 1e-5f);
    int p = h - 3; if (p < 0) p += 56;
    int q = w - 3; if (q < 0) q += 56;
    int row = (bb * 64 + (p / 7) * 8 + (q / 7)) * N_ + (p % 7) * 7 + (q % 7);
    float* out = g_hwin + (size_t)row * C_;
    for (int c = threadIdx.x; c < C_; c += blockDim.x)
        out[c] = (xi[c] - mean) * inv * g[c] + bt[c];
}

// ---------------- generic LN ----------------
__global__ void ln_kernel(const float* __restrict__ in, const float* __restrict__ g,
                          const float* __restrict__ bt, float* __restrict__ out, int F) {
    size_t base = (size_t)blockIdx.x * F;
    float s = 0.f, s2 = 0.f;
    for (int c = threadIdx.x; c < F; c += blockDim.x) { float v = in[base + c]; s += v; s2 += v * v; }
    blockReduce2(s, s2);
    float mean = s / F;
    float inv  = rsqrtf(s2 / F - mean * mean + 1e-5f);
    for (int c = threadIdx.x; c < F; c += blockDim.x)
        out[base + c] = (in[base + c] - mean) * inv * g[c] + bt[c];
}

// ---------------- SGEMM: C = A[M,K] @ W[K,N] + bias, EPI 0=none 1=gelu 2=+res ----
// BM=BN=64, BK=16, 256 threads, 4x4 microtile. All dims divide exactly.
template<int EPI>
__global__ void __launch_bounds__(256) sgemm64(
        const float* __restrict__ A, const float* __restrict__ W,
        const float* __restrict__ bias, const float* __restrict__ res,
        float* __restrict__ C, int M, int N, int K) {
    __shared__ float As[16][65];
    __shared__ float Bs[16][64];
    int tid = threadIdx.x;
    int rowBase = blockIdx.y * 64, colBase = blockIdx.x * 64;
    int arow = tid >> 2, ak4 = (tid & 3) * 4;
    int brow = tid >> 4, bc4 = (tid & 15) * 4;
    int ty = tid >> 4, tx = tid & 15;
    float acc[4][4] = {};
    for (int k0 = 0; k0 < K; k0 += 16) {
        float4 av = *(const float4*)&A[(size_t)(rowBase + arow) * K + k0 + ak4];
        As[ak4 + 0][arow] = av.x; As[ak4 + 1][arow] = av.y;
        As[ak4 + 2][arow] = av.z; As[ak4 + 3][arow] = av.w;
        float4 bv = *(const float4*)&W[(size_t)(k0 + brow) * N + colBase + bc4];
        *(float4*)&Bs[brow][bc4] = bv;
        __syncthreads();
        #pragma unroll
        for (int k = 0; k < 16; k++) {
            float a0 = As[k][ty * 4 + 0], a1 = As[k][ty * 4 + 1];
            float a2 = As[k][ty * 4 + 2], a3 = As[k][ty * 4 + 3];
            float4 b = *(float4*)&Bs[k][tx * 4];
            acc[0][0] += a0 * b.x; acc[0][1] += a0 * b.y; acc[0][2] += a0 * b.z; acc[0][3] += a0 * b.w;
            acc[1][0] += a1 * b.x; acc[1][1] += a1 * b.y; acc[1][2] += a1 * b.z; acc[1][3] += a1 * b.w;
            acc[2][0] += a2 * b.x; acc[2][1] += a2 * b.y; acc[2][2] += a2 * b.z; acc[2][3] += a2 * b.w;
            acc[3][0] += a3 * b.x; acc[3][1] += a3 * b.y; acc[3][2] += a3 * b.z; acc[3][3] += a3 * b.w;
        }
        __syncthreads();
    }
    #pragma unroll
    for (int i = 0; i < 4; i++) {
        int r = rowBase + ty * 4 + i;
        #pragma unroll
        for (int j = 0; j < 4; j++) {
            int c = colBase + tx * 4 + j;
            float v = acc[i][j] + bias[c];
            if (EPI == 1) v = 0.5f * v * (1.f + erff(v * 0.7071067811865476f));
            if (EPI == 2) v += res[(size_t)r * N + c];
            C[(size_t)r * N + c] = v;
        }
    }
}

// ---------------- attention: one block per (window, head) ----------------
__global__ void __launch_bounds__(256) attn_kernel(const float* __restrict__ rpb) {
    __shared__ float Ks[49 * 97];
    __shared__ float Vs[49 * 97];
    __shared__ float qs[8][96];
    __shared__ float sc[8][49];
    __shared__ int   cnt[49];
    int win  = blockIdx.x >> 2;
    int head = blockIdx.x & 3;
    int tid = threadIdx.x, lane = tid & 31, warp = tid >> 5;
    int wwin = win & 63, wh = wwin >> 3, ww = wwin & 7;
    if (tid < 49) {
        int i = tid / 7, j = tid % 7;
        int hc = wh * 7 + i, wc = ww * 7 + j;
        int rh = hc < 49 ? 0 : (hc < 53 ? 1 : 2);
        int rw = wc < 49 ? 0 : (wc < 53 ? 1 : 2);
        cnt[tid] = rh * 3 + rw;
    }
    const float* qkvw = g_qkv + (size_t)win * N_ * H3_;
    for (int idx = tid; idx < 49 * 96; idx += 256) {
        int j = idx / 96, d = idx % 96;
        Ks[j * 97 + d] = qkvw[(size_t)j * H3_ + C_      + head * HD_ + d];
        Vs[j * 97 + d] = qkvw[(size_t)j * H3_ + 2 * C_  + head * HD_ + d];
    }
    __syncthreads();
    const float scale = 0.1020620726159658f;  // 96^-0.5
    for (int i = warp; i < N_; i += 8) {
        qs[warp][lane     ] = qkvw[(size_t)i * H3_ + head * HD_ + lane     ];
        qs[warp][lane + 32] = qkvw[(size_t)i * H3_ + head * HD_ + lane + 32];
        qs[warp][lane + 64] = qkvw[(size_t)i * H3_ + head * HD_ + lane + 64];
        __syncwarp();
        int qi = i / 7, qj = i % 7;
        float s0, s1 = -1e30f;
        {
            int j = lane;
            float dot = 0.f;
            #pragma unroll 8
            for (int d = 0; d < 96; d++) dot += qs[warp][d] * Ks[j * 97 + d];
            int ki = j / 7, kj = j % 7;
            float bias = rpb[((qi - ki + 6) * 13 + (qj - kj + 6)) * NH_ + head];
            float msk  = (cnt[i] != cnt[j]) ? -100.f : 0.f;
            s0 = dot * scale + bias + msk;
        }
        if (lane < 17) {
            int j = lane + 32;
            float dot = 0.f;
            #pragma unroll 8
            for (int d = 0; d < 96; d++) dot += qs[warp][d] * Ks[j * 97 + d];
            int ki = j / 7, kj = j % 7;
            float bias = rpb[((qi - ki + 6) * 13 + (qj - kj + 6)) * NH_ + head];
            float msk  = (cnt[i] != cnt[j]) ? -100.f : 0.f;
            s1 = dot * scale + bias + msk;
        }
        float mx = fmaxf(s0, s1);
        #pragma unroll
        for (int o = 16; o > 0; o >>= 1) mx = fmaxf(mx, __shfl_xor_sync(0xffffffffu, mx, o));
        float e0 = expf(s0 - mx);
        float e1 = (lane < 17) ? expf(s1 - mx) : 0.f;
        float sum = e0 + e1;
        #pragma unroll
        for (int o = 16; o > 0; o >>= 1) sum += __shfl_xor_sync(0xffffffffu, sum, o);
        float rinv = 1.f / sum;
        sc[warp][lane] = e0 * rinv;
        if (lane < 17) sc[warp][lane + 32] = e1 * rinv;
        __syncwarp();
        float o0 = 0.f, o1 = 0.f, o2 = 0.f;
        #pragma unroll 7
        for (int j = 0; j < N_; j++) {
            float pv = sc[warp][j];
            o0 += pv * Vs[j * 97 + lane     ];
            o1 += pv * Vs[j * 97 + lane + 32];
            o2 += pv * Vs[j * 97 + lane + 64];
        }
        float* op = g_attn + (size_t)(win * N_ + i) * C_ + head * HD_;
        op[lane] = o0; op[lane + 32] = o1; op[lane + 64] = o2;
        __syncwarp();
    }
}

// ---------------- K4: un-partition + roll(+3,+3) + residual ----------------
__global__ void unshift_add(const float* __restrict__ x) {
    int t = blockIdx.x;
    int bb = t / 3136, rem = t % 3136, h = rem / 56, w = rem % 56;
    int p = h - 3; if (p < 0) p += 56;
    int q = w - 3; if (q < 0) q += 56;
    int row = (bb * 64 + (p / 7) * 8 + (q / 7)) * N_ + (p % 7) * 7 + (q % 7);
    const float* o  = g_owin + (size_t)row * C_;
    const float* xi = x      + (size_t)t   * C_;
    float* out = g_x1 + (size_t)t * C_;
    for (int c = threadIdx.x; c < C_; c += blockDim.x) out[c] = xi[c] + o[c];
}

// ---------------- launch ----------------
extern "C" void kernel_launch(void* const* d_in, const int* in_sizes, int n_in,
                              void* d_out, int out_size) {
    const float* x      = (const float*)d_in[0];
    const float* ln1_g  = (const float*)d_in[1];
    const float* ln1_b  = (const float*)d_in[2];
    const float* qkv_w  = (const float*)d_in[3];
    const float* qkv_b  = (const float*)d_in[4];
    const float* proj_w = (const float*)d_in[5];
    const float* proj_b = (const float*)d_in[6];
    const float* rpb    = (const float*)d_in[7];
    const float* ln2_g  = (const float*)d_in[8];
    const float* ln2_b  = (const float*)d_in[9];
    const float* fc1_w  = (const float*)d_in[10];
    const float* fc1_b  = (const float*)d_in[11];
    const float* ln3_g  = (const float*)d_in[12];
    const float* ln3_b  = (const float*)d_in[13];
    const float* fc2_w  = (const float*)d_in[14];
    const float* fc2_b  = (const float*)d_in[15];
    float* out = (float*)d_out;

    void *p_hwin, *p_qkv, *p_attn, *p_owin, *p_x1, *p_h2, *p_m1;
    cudaGetSymbolAddress(&p_hwin, g_hwin);
    cudaGetSymbolAddress(&p_qkv,  g_qkv);
    cudaGetSymbolAddress(&p_attn, g_attn);
    cudaGetSymbolAddress(&p_owin, g_owin);
    cudaGetSymbolAddress(&p_x1,   g_x1);
    cudaGetSymbolAddress(&p_h2,   g_h2);
    cudaGetSymbolAddress(&p_m1,   g_m1);

    ln1_part<<<NTOK, 128>>>(x, ln1_g, ln1_b);
    sgemm64<0><<<dim3(H3_ / 64, NTOK / 64), 256>>>(
        (const float*)p_hwin, qkv_w, qkv_b, nullptr, (float*)p_qkv, NTOK, H3_, C_);
    attn_kernel<<<NWIN * NH_, 256>>>(rpb);
    sgemm64<0><<<dim3(C_ / 64, NTOK / 64), 256>>>(
        (const float*)p_attn, proj_w, proj_b, nullptr, (float*)p_owin, NTOK, C_, C_);
    unshift_add<<<NTOK, 128>>>(x);
    ln_kernel<<<NTOK, 128>>>((const float*)p_x1, ln2_g, ln2_b, (float*)p_h2, C_);
    sgemm64<1><<<dim3(D_ / 64, NTOK / 64), 256>>>(
        (const float*)p_h2, fc1_w, fc1_b, nullptr, (float*)p_m1, NTOK, D_, C_);
    ln_kernel<<<NTOK, 256>>>((const float*)p_m1, ln3_g, ln3_b, (float*)p_m1, D_);
    sgemm64<2><<<dim3(C_ / 64, NTOK / 64), 256>>>(
        (const float*)p_m1, fc2_w, fc2_b, (const float*)p_x1, out, NTOK, C_, D_);
}

// round 6
// speedup vs baseline: 2.7432x; 2.7432x over previous
#include <cuda_runtime.h>
#include <math.h>
#include <stdint.h>

// ---------------- problem constants ----------------
#define C_    384
#define D_    1536
#define H3_   1152
#define NTOK  100352          // 32*56*56
#define NWIN  2048
#define N_    49
#define NH_   4
#define HD_   96

// ---------------- scratch ----------------
__device__ float g_hwin[(size_t)NTOK * C_];
__device__ float g_qkv [(size_t)NTOK * H3_];
__device__ float g_attn[(size_t)NTOK * C_];
__device__ float g_owin[(size_t)NTOK * C_];
__device__ float g_x1  [(size_t)NTOK * C_];
__device__ float g_h2  [(size_t)NTOK * C_];
__device__ float g_m1  [(size_t)NTOK * D_];

__device__ __forceinline__ uint32_t f2tf32(float f) {
    uint32_t u; asm("cvt.rna.tf32.f32 %0, %1;" : "=r"(u) : "f"(f)); return u;
}

__device__ __forceinline__ void mma_tf32(float* c, const uint32_t* a, uint32_t b0, uint32_t b1) {
    asm volatile("mma.sync.aligned.m16n8k8.row.col.f32.tf32.tf32.f32 "
        "{%0,%1,%2,%3}, {%4,%5,%6,%7}, {%8,%9}, {%0,%1,%2,%3};"
        : "+f"(c[0]), "+f"(c[1]), "+f"(c[2]), "+f"(c[3])
        : "r"(a[0]), "r"(a[1]), "r"(a[2]), "r"(a[3]), "r"(b0), "r"(b1));
}

// ---------------- tf32 mma.sync GEMM: C = A[M,K] @ W[K,N] + bias ----------------
// BM=BN=128, BK=32, 256 threads (8 warps 4x2, warp tile 32x64).
// EPI: 0=none, 1=gelu, 2=+res
#define SA 36      // A smem row stride (floats): bank=(4r+c)&31 conflict-free
#define SB 136     // B smem row stride (floats): 136%32=8 -> bank=(8k+n)&31 conflict-free

template<int EPI>
__global__ void __launch_bounds__(256) mmagemm(
        const float* __restrict__ A, const float* __restrict__ W,
        const float* __restrict__ bias, const float* __restrict__ res,
        float* __restrict__ C, int M, int N, int K) {
    __shared__ float As[128 * SA];
    __shared__ float Bs[32 * SB];
    const int tid = threadIdx.x;
    const int lane = tid & 31, wid = tid >> 5;
    const int warpM = wid & 3, warpN = wid >> 2;
    const int rowBase = blockIdx.y * 128, colBase = blockIdx.x * 128;
    const int g = lane >> 2, t = lane & 3;

    float acc[2][8][4] = {};

    for (int k0 = 0; k0 < K; k0 += 32) {
        // ---- A tile: 128x32 floats, 1024 float4, 4/thread ----
        #pragma unroll
        for (int j = 0; j < 4; j++) {
            int f = tid + j * 256;
            int r = f >> 3, c4 = f & 7;
            float4 v = *(const float4*)&A[(size_t)(rowBase + r) * K + k0 + c4 * 4];
            float4 u;
            u.x = __uint_as_float(f2tf32(v.x)); u.y = __uint_as_float(f2tf32(v.y));
            u.z = __uint_as_float(f2tf32(v.z)); u.w = __uint_as_float(f2tf32(v.w));
            *(float4*)&As[r * SA + c4 * 4] = u;
        }
        // ---- B tile: 32x128 floats, 1024 float4, 4/thread ----
        #pragma unroll
        for (int j = 0; j < 4; j++) {
            int f = tid + j * 256;
            int k = f >> 5, n4 = f & 31;
            float4 v = *(const float4*)&W[(size_t)(k0 + k) * N + colBase + n4 * 4];
            float4 u;
            u.x = __uint_as_float(f2tf32(v.x)); u.y = __uint_as_float(f2tf32(v.y));
            u.z = __uint_as_float(f2tf32(v.z)); u.w = __uint_as_float(f2tf32(v.w));
            *(float4*)&Bs[k * SB + n4 * 4] = u;
        }
        __syncthreads();

        #pragma unroll
        for (int ks = 0; ks < 4; ks++) {
            int kk = ks * 8;
            uint32_t a[2][4];
            #pragma unroll
            for (int mi = 0; mi < 2; mi++) {
                int rr = warpM * 32 + mi * 16;
                a[mi][0] = __float_as_uint(As[(rr + g    ) * SA + kk + t    ]);
                a[mi][1] = __float_as_uint(As[(rr + g + 8) * SA + kk + t    ]);
                a[mi][2] = __float_as_uint(As[(rr + g    ) * SA + kk + t + 4]);
                a[mi][3] = __float_as_uint(As[(rr + g + 8) * SA + kk + t + 4]);
            }
            #pragma unroll
            for (int ni = 0; ni < 8; ni++) {
                int cc = warpN * 64 + ni * 8 + g;
                uint32_t b0 = __float_as_uint(Bs[(kk + t    ) * SB + cc]);
                uint32_t b1 = __float_as_uint(Bs[(kk + t + 4) * SB + cc]);
                mma_tf32(acc[0][ni], a[0], b0, b1);
                mma_tf32(acc[1][ni], a[1], b0, b1);
            }
        }
        __syncthreads();
    }

    // ---- epilogue ----
    #pragma unroll
    for (int mi = 0; mi < 2; mi++) {
        int row0 = rowBase + warpM * 32 + mi * 16 + g;
        int row1 = row0 + 8;
        #pragma unroll
        for (int ni = 0; ni < 8; ni++) {
            int col = colBase + warpN * 64 + ni * 8 + 2 * t;
            float b0 = bias[col], b1 = bias[col + 1];
            float v0 = acc[mi][ni][0] + b0;
            float v1 = acc[mi][ni][1] + b1;
            float v2 = acc[mi][ni][2] + b0;
            float v3 = acc[mi][ni][3] + b1;
            if (EPI == 1) {
                v0 = 0.5f * v0 * (1.f + erff(v0 * 0.7071067811865476f));
                v1 = 0.5f * v1 * (1.f + erff(v1 * 0.7071067811865476f));
                v2 = 0.5f * v2 * (1.f + erff(v2 * 0.7071067811865476f));
                v3 = 0.5f * v3 * (1.f + erff(v3 * 0.7071067811865476f));
            }
            if (EPI == 2) {
                float2 r0 = *(const float2*)&res[(size_t)row0 * N + col];
                float2 r1 = *(const float2*)&res[(size_t)row1 * N + col];
                v0 += r0.x; v1 += r0.y; v2 += r1.x; v3 += r1.y;
            }
            *(float2*)&C[(size_t)row0 * N + col] = make_float2(v0, v1);
            *(float2*)&C[(size_t)row1 * N + col] = make_float2(v2, v3);
        }
    }
}

// ---------------- block reduce (sum, sumsq) ----------------
__device__ __forceinline__ void blockReduce2(float &a, float &b) {
    #pragma unroll
    for (int o = 16; o > 0; o >>= 1) {
        a += __shfl_down_sync(0xffffffffu, a, o);
        b += __shfl_down_sync(0xffffffffu, b, o);
    }
    __shared__ float sa[32], sb[32];
    int lane = threadIdx.x & 31, wid = threadIdx.x >> 5;
    if (lane == 0) { sa[wid] = a; sb[wid] = b; }
    __syncthreads();
    int nw = blockDim.x >> 5;
    if (wid == 0) {
        a = (lane < nw) ? sa[lane] : 0.f;
        b = (lane < nw) ? sb[lane] : 0.f;
        #pragma unroll
        for (int o = 16; o > 0; o >>= 1) {
            a += __shfl_down_sync(0xffffffffu, a, o);
            b += __shfl_down_sync(0xffffffffu, b, o);
        }
        if (lane == 0) { sa[0] = a; sb[0] = b; }
    }
    __syncthreads();
    a = sa[0]; b = sb[0];
}

// ---------------- K1: LN1 + roll(-3,-3) + window partition ----------------
__global__ void ln1_part(const float* __restrict__ x,
                         const float* __restrict__ g, const float* __restrict__ bt) {
    int t = blockIdx.x;
    int bb = t / 3136, rem = t % 3136, h = rem / 56, w = rem % 56;
    const float* xi = x + (size_t)t * C_;
    float s = 0.f, s2 = 0.f;
    for (int c = threadIdx.x; c < C_; c += blockDim.x) { float v = xi[c]; s += v; s2 += v * v; }
    blockReduce2(s, s2);
    float mean = s * (1.f / C_);
    float inv  = rsqrtf(s2 * (1.f / C_) - mean * mean + 1e-5f);
    int p = h - 3; if (p < 0) p += 56;
    int q = w - 3; if (q < 0) q += 56;
    int row = (bb * 64 + (p / 7) * 8 + (q / 7)) * N_ + (p % 7) * 7 + (q % 7);
    float* out = g_hwin + (size_t)row * C_;
    for (int c = threadIdx.x; c < C_; c += blockDim.x)
        out[c] = (xi[c] - mean) * inv * g[c] + bt[c];
}

// ---------------- generic LN ----------------
__global__ void ln_kernel(const float* __restrict__ in, const float* __restrict__ g,
                          const float* __restrict__ bt, float* __restrict__ out, int F) {
    size_t base = (size_t)blockIdx.x * F;
    float s = 0.f, s2 = 0.f;
    for (int c = threadIdx.x; c < F; c += blockDim.x) { float v = in[base + c]; s += v; s2 += v * v; }
    blockReduce2(s, s2);
    float mean = s / F;
    float inv  = rsqrtf(s2 / F - mean * mean + 1e-5f);
    for (int c = threadIdx.x; c < F; c += blockDim.x)
        out[base + c] = (in[base + c] - mean) * inv * g[c] + bt[c];
}

// ---------------- attention: one block per (window, head) ----------------
__global__ void __launch_bounds__(256) attn_kernel(const float* __restrict__ rpb) {
    __shared__ float Ks[49 * 97];
    __shared__ float Vs[49 * 97];
    __shared__ float qs[8][96];
    __shared__ float sc[8][49];
    __shared__ int   cnt[49];
    int win  = blockIdx.x >> 2;
    int head = blockIdx.x & 3;
    int tid = threadIdx.x, lane = tid & 31, warp = tid >> 5;
    int wwin = win & 63, wh = wwin >> 3, ww = wwin & 7;
    if (tid < 49) {
        int i = tid / 7, j = tid % 7;
        int hc = wh * 7 + i, wc = ww * 7 + j;
        int rh = hc < 49 ? 0 : (hc < 53 ? 1 : 2);
        int rw = wc < 49 ? 0 : (wc < 53 ? 1 : 2);
        cnt[tid] = rh * 3 + rw;
    }
    const float* qkvw = g_qkv + (size_t)win * N_ * H3_;
    for (int idx = tid; idx < 49 * 96; idx += 256) {
        int j = idx / 96, d = idx % 96;
        Ks[j * 97 + d] = qkvw[(size_t)j * H3_ + C_      + head * HD_ + d];
        Vs[j * 97 + d] = qkvw[(size_t)j * H3_ + 2 * C_  + head * HD_ + d];
    }
    __syncthreads();
    const float scale = 0.1020620726159658f;
    for (int i = warp; i < N_; i += 8) {
        qs[warp][lane     ] = qkvw[(size_t)i * H3_ + head * HD_ + lane     ];
        qs[warp][lane + 32] = qkvw[(size_t)i * H3_ + head * HD_ + lane + 32];
        qs[warp][lane + 64] = qkvw[(size_t)i * H3_ + head * HD_ + lane + 64];
        __syncwarp();
        int qi = i / 7, qj = i % 7;
        float s0, s1 = -1e30f;
        {
            int j = lane;
            float dot = 0.f;
            #pragma unroll 8
            for (int d = 0; d < 96; d++) dot += qs[warp][d] * Ks[j * 97 + d];
            int ki = j / 7, kj = j % 7;
            float bias = rpb[((qi - ki + 6) * 13 + (qj - kj + 6)) * NH_ + head];
            float msk  = (cnt[i] != cnt[j]) ? -100.f : 0.f;
            s0 = dot * scale + bias + msk;
        }
        if (lane < 17) {
            int j = lane + 32;
            float dot = 0.f;
            #pragma unroll 8
            for (int d = 0; d < 96; d++) dot += qs[warp][d] * Ks[j * 97 + d];
            int ki = j / 7, kj = j % 7;
            float bias = rpb[((qi - ki + 6) * 13 + (qj - kj + 6)) * NH_ + head];
            float msk  = (cnt[i] != cnt[j]) ? -100.f : 0.f;
            s1 = dot * scale + bias + msk;
        }
        float mx = fmaxf(s0, s1);
        #pragma unroll
        for (int o = 16; o > 0; o >>= 1) mx = fmaxf(mx, __shfl_xor_sync(0xffffffffu, mx, o));
        float e0 = expf(s0 - mx);
        float e1 = (lane < 17) ? expf(s1 - mx) : 0.f;
        float sum = e0 + e1;
        #pragma unroll
        for (int o = 16; o > 0; o >>= 1) sum += __shfl_xor_sync(0xffffffffu, sum, o);
        float rinv = 1.f / sum;
        sc[warp][lane] = e0 * rinv;
        if (lane < 17) sc[warp][lane + 32] = e1 * rinv;
        __syncwarp();
        float o0 = 0.f, o1 = 0.f, o2 = 0.f;
        #pragma unroll 7
        for (int j = 0; j < N_; j++) {
            float pv = sc[warp][j];
            o0 += pv * Vs[j * 97 + lane     ];
            o1 += pv * Vs[j * 97 + lane + 32];
            o2 += pv * Vs[j * 97 + lane + 64];
        }
        float* op = g_attn + (size_t)(win * N_ + i) * C_ + head * HD_;
        op[lane] = o0; op[lane + 32] = o1; op[lane + 64] = o2;
        __syncwarp();
    }
}

// ---------------- K4: un-partition + roll(+3,+3) + residual ----------------
__global__ void unshift_add(const float* __restrict__ x) {
    int t = blockIdx.x;
    int bb = t / 3136, rem = t % 3136, h = rem / 56, w = rem % 56;
    int p = h - 3; if (p < 0) p += 56;
    int q = w - 3; if (q < 0) q += 56;
    int row = (bb * 64 + (p / 7) * 8 + (q / 7)) * N_ + (p % 7) * 7 + (q % 7);
    const float* o  = g_owin + (size_t)row * C_;
    const float* xi = x      + (size_t)t   * C_;
    float* out = g_x1 + (size_t)t * C_;
    for (int c = threadIdx.x; c < C_; c += blockDim.x) out[c] = xi[c] + o[c];
}

// ---------------- launch ----------------
extern "C" void kernel_launch(void* const* d_in, const int* in_sizes, int n_in,
                              void* d_out, int out_size) {
    const float* x      = (const float*)d_in[0];
    const float* ln1_g  = (const float*)d_in[1];
    const float* ln1_b  = (const float*)d_in[2];
    const float* qkv_w  = (const float*)d_in[3];
    const float* qkv_b  = (const float*)d_in[4];
    const float* proj_w = (const float*)d_in[5];
    const float* proj_b = (const float*)d_in[6];
    const float* rpb    = (const float*)d_in[7];
    const float* ln2_g  = (const float*)d_in[8];
    const float* ln2_b  = (const float*)d_in[9];
    const float* fc1_w  = (const float*)d_in[10];
    const float* fc1_b  = (const float*)d_in[11];
    const float* ln3_g  = (const float*)d_in[12];
    const float* ln3_b  = (const float*)d_in[13];
    const float* fc2_w  = (const float*)d_in[14];
    const float* fc2_b  = (const float*)d_in[15];
    float* out = (float*)d_out;

    void *p_hwin, *p_qkv, *p_attn, *p_owin, *p_x1, *p_h2, *p_m1;
    cudaGetSymbolAddress(&p_hwin, g_hwin);
    cudaGetSymbolAddress(&p_qkv,  g_qkv);
    cudaGetSymbolAddress(&p_attn, g_attn);
    cudaGetSymbolAddress(&p_owin, g_owin);
    cudaGetSymbolAddress(&p_x1,   g_x1);
    cudaGetSymbolAddress(&p_h2,   g_h2);
    cudaGetSymbolAddress(&p_m1,   g_m1);

    ln1_part<<<NTOK, 128>>>(x, ln1_g, ln1_b);
    mmagemm<0><<<dim3(H3_ / 128, NTOK / 128), 256>>>(
        (const float*)p_hwin, qkv_w, qkv_b, nullptr, (float*)p_qkv, NTOK, H3_, C_);
    attn_kernel<<<NWIN * NH_, 256>>>(rpb);
    mmagemm<0><<<dim3(C_ / 128, NTOK / 128), 256>>>(
        (const float*)p_attn, proj_w, proj_b, nullptr, (float*)p_owin, NTOK, C_, C_);
    unshift_add<<<NTOK, 128>>>(x);
    ln_kernel<<<NTOK, 128>>>((const float*)p_x1, ln2_g, ln2_b, (float*)p_h2, C_);
    mmagemm<1><<<dim3(D_ / 128, NTOK / 128), 256>>>(
        (const float*)p_h2, fc1_w, fc1_b, nullptr, (float*)p_m1, NTOK, D_, C_);
    ln_kernel<<<NTOK, 256>>>((const float*)p_m1, ln3_g, ln3_b, (float*)p_m1, D_);
    mmagemm<2><<<dim3(C_ / 128, NTOK / 128), 256>>>(
        (const float*)p_m1, fc2_w, fc2_b, (const float*)p_x1, out, NTOK, C_, D_);
}

// round 7
// speedup vs baseline: 2.7686x; 1.0093x over previous
#include <cuda_runtime.h>
#include <math.h>
#include <stdint.h>

// ---------------- problem constants ----------------
#define C_    384
#define D_    1536
#define H3_   1152
#define NTOK  100352          // 32*56*56
#define NWIN  2048
#define N_    49
#define NH_   4
#define HD_   96

// ---------------- scratch ----------------
__device__ float g_hwin[(size_t)NTOK * C_];
__device__ float g_qkv [(size_t)NTOK * H3_];
__device__ float g_attn[(size_t)NTOK * C_];
__device__ float g_owin[(size_t)NTOK * C_];
__device__ float g_x1  [(size_t)NTOK * C_];
__device__ float g_h2  [(size_t)NTOK * C_];
__device__ float g_m1  [(size_t)NTOK * D_];

__device__ __forceinline__ uint32_t f2tf32(float f) {
    uint32_t u; asm("cvt.rna.tf32.f32 %0, %1;" : "=r"(u) : "f"(f)); return u;
}

__device__ __forceinline__ void mma_tf32(float* c, const uint32_t* a, uint32_t b0, uint32_t b1) {
    asm volatile("mma.sync.aligned.m16n8k8.row.col.f32.tf32.tf32.f32 "
        "{%0,%1,%2,%3}, {%4,%5,%6,%7}, {%8,%9}, {%0,%1,%2,%3};"
        : "+f"(c[0]), "+f"(c[1]), "+f"(c[2]), "+f"(c[3])
        : "r"(a[0]), "r"(a[1]), "r"(a[2]), "r"(a[3]), "r"(b0), "r"(b1));
}

// ---------------- tf32 mma.sync GEMM: C = A[M,K] @ W[K,N] + bias ----------------
// BM=BN=128, BK=32, 256 threads (8 warps 4x2, warp tile 32x64).
// EPI: 0=none, 1=gelu, 2=+res
#define SA 36      // A smem row stride (floats): bank=(4r+c)&31 conflict-free
#define SB 136     // B smem row stride (floats): 136%32=8 -> bank=(8k+n)&31 conflict-free

template<int EPI>
__global__ void __launch_bounds__(256) mmagemm(
        const float* __restrict__ A, const float* __restrict__ W,
        const float* __restrict__ bias, const float* __restrict__ res,
        float* __restrict__ C, int M, int N, int K) {
    __shared__ float As[128 * SA];
    __shared__ float Bs[32 * SB];
    const int tid = threadIdx.x;
    const int lane = tid & 31, wid = tid >> 5;
    const int warpM = wid & 3, warpN = wid >> 2;
    const int rowBase = blockIdx.y * 128, colBase = blockIdx.x * 128;
    const int g = lane >> 2, t = lane & 3;

    float acc[2][8][4] = {};

    for (int k0 = 0; k0 < K; k0 += 32) {
        // ---- A tile: 128x32 floats, 1024 float4, 4/thread ----
        #pragma unroll
        for (int j = 0; j < 4; j++) {
            int f = tid + j * 256;
            int r = f >> 3, c4 = f & 7;
            float4 v = *(const float4*)&A[(size_t)(rowBase + r) * K + k0 + c4 * 4];
            float4 u;
            u.x = __uint_as_float(f2tf32(v.x)); u.y = __uint_as_float(f2tf32(v.y));
            u.z = __uint_as_float(f2tf32(v.z)); u.w = __uint_as_float(f2tf32(v.w));
            *(float4*)&As[r * SA + c4 * 4] = u;
        }
        // ---- B tile: 32x128 floats, 1024 float4, 4/thread ----
        #pragma unroll
        for (int j = 0; j < 4; j++) {
            int f = tid + j * 256;
            int k = f >> 5, n4 = f & 31;
            float4 v = *(const float4*)&W[(size_t)(k0 + k) * N + colBase + n4 * 4];
            float4 u;
            u.x = __uint_as_float(f2tf32(v.x)); u.y = __uint_as_float(f2tf32(v.y));
            u.z = __uint_as_float(f2tf32(v.z)); u.w = __uint_as_float(f2tf32(v.w));
            *(float4*)&Bs[k * SB + n4 * 4] = u;
        }
        __syncthreads();

        #pragma unroll
        for (int ks = 0; ks < 4; ks++) {
            int kk = ks * 8;
            uint32_t a[2][4];
            #pragma unroll
            for (int mi = 0; mi < 2; mi++) {
                int rr = warpM * 32 + mi * 16;
                a[mi][0] = __float_as_uint(As[(rr + g    ) * SA + kk + t    ]);
                a[mi][1] = __float_as_uint(As[(rr + g + 8) * SA + kk + t    ]);
                a[mi][2] = __float_as_uint(As[(rr + g    ) * SA + kk + t + 4]);
                a[mi][3] = __float_as_uint(As[(rr + g + 8) * SA + kk + t + 4]);
            }
            #pragma unroll
            for (int ni = 0; ni < 8; ni++) {
                int cc = warpN * 64 + ni * 8 + g;
                uint32_t b0 = __float_as_uint(Bs[(kk + t    ) * SB + cc]);
                uint32_t b1 = __float_as_uint(Bs[(kk + t + 4) * SB + cc]);
                mma_tf32(acc[0][ni], a[0], b0, b1);
                mma_tf32(acc[1][ni], a[1], b0, b1);
            }
        }
        __syncthreads();
    }

    // ---- epilogue ----
    #pragma unroll
    for (int mi = 0; mi < 2; mi++) {
        int row0 = rowBase + warpM * 32 + mi * 16 + g;
        int row1 = row0 + 8;
        #pragma unroll
        for (int ni = 0; ni < 8; ni++) {
            int col = colBase + warpN * 64 + ni * 8 + 2 * t;
            float b0 = bias[col], b1 = bias[col + 1];
            float v0 = acc[mi][ni][0] + b0;
            float v1 = acc[mi][ni][1] + b1;
            float v2 = acc[mi][ni][2] + b0;
            float v3 = acc[mi][ni][3] + b1;
            if (EPI == 1) {
                v0 = 0.5f * v0 * (1.f + erff(v0 * 0.7071067811865476f));
                v1 = 0.5f * v1 * (1.f + erff(v1 * 0.7071067811865476f));
                v2 = 0.5f * v2 * (1.f + erff(v2 * 0.7071067811865476f));
                v3 = 0.5f * v3 * (1.f + erff(v3 * 0.7071067811865476f));
            }
            if (EPI == 2) {
                float2 r0 = *(const float2*)&res[(size_t)row0 * N + col];
                float2 r1 = *(const float2*)&res[(size_t)row1 * N + col];
                v0 += r0.x; v1 += r0.y; v2 += r1.x; v3 += r1.y;
            }
            *(float2*)&C[(size_t)row0 * N + col] = make_float2(v0, v1);
            *(float2*)&C[(size_t)row1 * N + col] = make_float2(v2, v3);
        }
    }
}

// ---------------- block reduce (sum, sumsq) ----------------
__device__ __forceinline__ void blockReduce2(float &a, float &b) {
    #pragma unroll
    for (int o = 16; o > 0; o >>= 1) {
        a += __shfl_down_sync(0xffffffffu, a, o);
        b += __shfl_down_sync(0xffffffffu, b, o);
    }
    __shared__ float sa[32], sb[32];
    int lane = threadIdx.x & 31, wid = threadIdx.x >> 5;
    if (lane == 0) { sa[wid] = a; sb[wid] = b; }
    __syncthreads();
    int nw = blockDim.x >> 5;
    if (wid == 0) {
        a = (lane < nw) ? sa[lane] : 0.f;
        b = (lane < nw) ? sb[lane] : 0.f;
        #pragma unroll
        for (int o = 16; o > 0; o >>= 1) {
            a += __shfl_down_sync(0xffffffffu, a, o);
            b += __shfl_down_sync(0xffffffffu, b, o);
        }
        if (lane == 0) { sa[0] = a; sb[0] = b; }
    }
    __syncthreads();
    a = sa[0]; b = sb[0];
}

// ---------------- K1: LN1 + roll(-3,-3) + window partition ----------------
__global__ void ln1_part(const float* __restrict__ x,
                         const float* __restrict__ g, const float* __restrict__ bt) {
    int t = blockIdx.x;
    int bb = t / 3136, rem = t % 3136, h = rem / 56, w = rem % 56;
    const float* xi = x + (size_t)t * C_;
    float s = 0.f, s2 = 0.f;
    for (int c = threadIdx.x; c < C_; c += blockDim.x) { float v = xi[c]; s += v; s2 += v * v; }
    blockReduce2(s, s2);
    float mean = s * (1.f / C_);
    float inv  = rsqrtf(s2 * (1.f / C_) - mean * mean + 1e-5f);
    int p = h - 3; if (p < 0) p += 56;
    int q = w - 3; if (q < 0) q += 56;
    int row = (bb * 64 + (p / 7) * 8 + (q / 7)) * N_ + (p % 7) * 7 + (q % 7);
    float* out = g_hwin + (size_t)row * C_;
    for (int c = threadIdx.x; c < C_; c += blockDim.x)
        out[c] = (xi[c] - mean) * inv * g[c] + bt[c];
}

// ---------------- generic LN ----------------
__global__ void ln_kernel(const float* __restrict__ in, const float* __restrict__ g,
                          const float* __restrict__ bt, float* __restrict__ out, int F) {
    size_t base = (size_t)blockIdx.x * F;
    float s = 0.f, s2 = 0.f;
    for (int c = threadIdx.x; c < F; c += blockDim.x) { float v = in[base + c]; s += v; s2 += v * v; }
    blockReduce2(s, s2);
    float mean = s / F;
    float inv  = rsqrtf(s2 / F - mean * mean + 1e-5f);
    for (int c = threadIdx.x; c < F; c += blockDim.x)
        out[base + c] = (in[base + c] - mean) * inv * g[c] + bt[c];
}

// ---------------- attention: one block per (window, head) ----------------
__global__ void __launch_bounds__(256) attn_kernel(const float* __restrict__ rpb) {
    __shared__ float Ks[49 * 97];
    __shared__ float Vs[49 * 97];
    __shared__ float qs[8][96];
    __shared__ float sc[8][49];
    __shared__ int   cnt[49];
    int win  = blockIdx.x >> 2;
    int head = blockIdx.x & 3;
    int tid = threadIdx.x, lane = tid & 31, warp = tid >> 5;
    int wwin = win & 63, wh = wwin >> 3, ww = wwin & 7;
    if (tid < 49) {
        int i = tid / 7, j = tid % 7;
        int hc = wh * 7 + i, wc = ww * 7 + j;
        int rh = hc < 49 ? 0 : (hc < 53 ? 1 : 2);
        int rw = wc < 49 ? 0 : (wc < 53 ? 1 : 2);
        cnt[tid] = rh * 3 + rw;
    }
    const float* qkvw = g_qkv + (size_t)win * N_ * H3_;
    for (int idx = tid; idx < 49 * 96; idx += 256) {
        int j = idx / 96, d = idx % 96;
        Ks[j * 97 + d] = qkvw[(size_t)j * H3_ + C_      + head * HD_ + d];
        Vs[j * 97 + d] = qkvw[(size_t)j * H3_ + 2 * C_  + head * HD_ + d];
    }
    __syncthreads();
    const float scale = 0.1020620726159658f;
    for (int i = warp; i < N_; i += 8) {
        qs[warp][lane     ] = qkvw[(size_t)i * H3_ + head * HD_ + lane     ];
        qs[warp][lane + 32] = qkvw[(size_t)i * H3_ + head * HD_ + lane + 32];
        qs[warp][lane + 64] = qkvw[(size_t)i * H3_ + head * HD_ + lane + 64];
        __syncwarp();
        int qi = i / 7, qj = i % 7;
        float s0, s1 = -1e30f;
        {
            int j = lane;
            float dot = 0.f;
            #pragma unroll 8
            for (int d = 0; d < 96; d++) dot += qs[warp][d] * Ks[j * 97 + d];
            int ki = j / 7, kj = j % 7;
            float bias = rpb[((qi - ki + 6) * 13 + (qj - kj + 6)) * NH_ + head];
            float msk  = (cnt[i] != cnt[j]) ? -100.f : 0.f;
            s0 = dot * scale + bias + msk;
        }
        if (lane < 17) {
            int j = lane + 32;
            float dot = 0.f;
            #pragma unroll 8
            for (int d = 0; d < 96; d++) dot += qs[warp][d] * Ks[j * 97 + d];
            int ki = j / 7, kj = j % 7;
            float bias = rpb[((qi - ki + 6) * 13 + (qj - kj + 6)) * NH_ + head];
            float msk  = (cnt[i] != cnt[j]) ? -100.f : 0.f;
            s1 = dot * scale + bias + msk;
        }
        float mx = fmaxf(s0, s1);
        #pragma unroll
        for (int o = 16; o > 0; o >>= 1) mx = fmaxf(mx, __shfl_xor_sync(0xffffffffu, mx, o));
        float e0 = expf(s0 - mx);
        float e1 = (lane < 17) ? expf(s1 - mx) : 0.f;
        float sum = e0 + e1;
        #pragma unroll
        for (int o = 16; o > 0; o >>= 1) sum += __shfl_xor_sync(0xffffffffu, sum, o);
        float rinv = 1.f / sum;
        sc[warp][lane] = e0 * rinv;
        if (lane < 17) sc[warp][lane + 32] = e1 * rinv;
        __syncwarp();
        float o0 = 0.f, o1 = 0.f, o2 = 0.f;
        #pragma unroll 7
        for (int j = 0; j < N_; j++) {
            float pv = sc[warp][j];
            o0 += pv * Vs[j * 97 + lane     ];
            o1 += pv * Vs[j * 97 + lane + 32];
            o2 += pv * Vs[j * 97 + lane + 64];
        }
        float* op = g_attn + (size_t)(win * N_ + i) * C_ + head * HD_;
        op[lane] = o0; op[lane + 32] = o1; op[lane + 64] = o2;
        __syncwarp();
    }
}

// ---------------- K4: un-partition + roll(+3,+3) + residual ----------------
__global__ void unshift_add(const float* __restrict__ x) {
    int t = blockIdx.x;
    int bb = t / 3136, rem = t % 3136, h = rem / 56, w = rem % 56;
    int p = h - 3; if (p < 0) p += 56;
    int q = w - 3; if (q < 0) q += 56;
    int row = (bb * 64 + (p / 7) * 8 + (q / 7)) * N_ + (p % 7) * 7 + (q % 7);
    const float* o  = g_owin + (size_t)row * C_;
    const float* xi = x      + (size_t)t   * C_;
    float* out = g_x1 + (size_t)t * C_;
    for (int c = threadIdx.x; c < C_; c += blockDim.x) out[c] = xi[c] + o[c];
}

// ---------------- launch ----------------
extern "C" void kernel_launch(void* const* d_in, const int* in_sizes, int n_in,
                              void* d_out, int out_size) {
    const float* x      = (const float*)d_in[0];
    const float* ln1_g  = (const float*)d_in[1];
    const float* ln1_b  = (const float*)d_in[2];
    const float* qkv_w  = (const float*)d_in[3];
    const float* qkv_b  = (const float*)d_in[4];
    const float* proj_w = (const float*)d_in[5];
    const float* proj_b = (const float*)d_in[6];
    const float* rpb    = (const float*)d_in[7];
    const float* ln2_g  = (const float*)d_in[8];
    const float* ln2_b  = (const float*)d_in[9];
    const float* fc1_w  = (const float*)d_in[10];
    const float* fc1_b  = (const float*)d_in[11];
    const float* ln3_g  = (const float*)d_in[12];
    const float* ln3_b  = (const float*)d_in[13];
    const float* fc2_w  = (const float*)d_in[14];
    const float* fc2_b  = (const float*)d_in[15];
    float* out = (float*)d_out;

    void *p_hwin, *p_qkv, *p_attn, *p_owin, *p_x1, *p_h2, *p_m1;
    cudaGetSymbolAddress(&p_hwin, g_hwin);
    cudaGetSymbolAddress(&p_qkv,  g_qkv);
    cudaGetSymbolAddress(&p_attn, g_attn);
    cudaGetSymbolAddress(&p_owin, g_owin);
    cudaGetSymbolAddress(&p_x1,   g_x1);
    cudaGetSymbolAddress(&p_h2,   g_h2);
    cudaGetSymbolAddress(&p_m1,   g_m1);

    ln1_part<<<NTOK, 128>>>(x, ln1_g, ln1_b);
    mmagemm<0><<<dim3(H3_ / 128, NTOK / 128), 256>>>(
        (const float*)p_hwin, qkv_w, qkv_b, nullptr, (float*)p_qkv, NTOK, H3_, C_);
    attn_kernel<<<NWIN * NH_, 256>>>(rpb);
    mmagemm<0><<<dim3(C_ / 128, NTOK / 128), 256>>>(
        (const float*)p_attn, proj_w, proj_b, nullptr, (float*)p_owin, NTOK, C_, C_);
    unshift_add<<<NTOK, 128>>>(x);
    ln_kernel<<<NTOK, 128>>>((const float*)p_x1, ln2_g, ln2_b, (float*)p_h2, C_);
    mmagemm<1><<<dim3(D_ / 128, NTOK / 128), 256>>>(
        (const float*)p_h2, fc1_w, fc1_b, nullptr, (float*)p_m1, NTOK, D_, C_);
    ln_kernel<<<NTOK, 256>>>((const float*)p_m1, ln3_g, ln3_b, (float*)p_m1, D_);
    mmagemm<2><<<dim3(C_ / 128, NTOK / 128), 256>>>(
        (const float*)p_m1, fc2_w, fc2_b, (const float*)p_x1, out, NTOK, C_, D_);
}